// round 17
// baseline (speedup 1.0000x reference)
#include <cuda_runtime.h>
#include <cuda_bf16.h>
#include <cstdint>

#define HWc   4096
#define NPIX  16384   // B*H*W
#define Cc    256
#define CPc   32
#define EPSc  1e-5f

__device__ float g_km[NPIX*CPc];
__device__ float g_qm[NPIX*CPc];
__device__ float g_xm[NPIX*CPc];
__device__ float g_pre[NPIX*CPc];
__device__ float g_w[NPIX*96];    // per-pixel combined softmax weights (81 used)
__device__ float g_part[64*1056];
__device__ float g_ab[2*Cc];
__device__ unsigned int g_cnt;   // zero-init; self-resets each call

static __device__ __forceinline__ uint32_t smem_u32(const void* p) {
    uint32_t a;
    asm("{ .reg .u64 tmp; cvta.to.shared.u64 tmp, %1; cvt.u32.u64 %0, tmp; }"
        : "=r"(a) : "l"(p));
    return a;
}

#define LDMX4(r0,r1,r2,r3,addr) \
    asm volatile("ldmatrix.sync.aligned.m8n8.x4.shared.b16 {%0,%1,%2,%3}, [%4];" \
        : "=r"(r0),"=r"(r1),"=r"(r2),"=r"(r3) : "r"(addr))
#define LDMX2(r0,r1,addr) \
    asm volatile("ldmatrix.sync.aligned.m8n8.x2.shared.b16 {%0,%1}, [%2];" \
        : "=r"(r0),"=r"(r1) : "r"(addr))
#define MMA16816(C,a0,a1,a2,a3,b0,b1) \
    asm volatile("mma.sync.aligned.m16n8k16.row.col.f32.bf16.bf16.f32 " \
        "{%0,%1,%2,%3}, {%4,%5,%6,%7}, {%8,%9}, {%0,%1,%2,%3};" \
        : "+f"((C)[0]), "+f"((C)[1]), "+f"((C)[2]), "+f"((C)[3]) \
        : "r"(a0),"r"(a1),"r"(a2),"r"(a3), "r"(b0),"r"(b1))

// ---------------------------------------------------------------------------
// K1 (HMMA): km/qm/xm conv1x1, split-bf16.  (R15/R16 PROVEN, unchanged)
// ---------------------------------------------------------------------------
__global__ void __launch_bounds__(256) k1_kqx_mma(
    const float* __restrict__ x, const float* __restrict__ vessel,
    const float* __restrict__ wk, const float* __restrict__ bk,
    const float* __restrict__ wq, const float* __restrict__ bq,
    const float* __restrict__ wx, const float* __restrict__ bx)
{
    __shared__ __align__(16) __nv_bfloat16 Ah[64*72], Al[64*72];
    __shared__ __align__(16) __nv_bfloat16 Bh[96*72], Bl[96*72];
    __shared__ float bs[96], vs[64];

    int t = threadIdx.x;
    int w = t >> 5, lane = t & 31;
    int p0 = blockIdx.x * 64;
    const float* xb = x + (size_t)(p0 >> 12)*(Cc*HWc) + (p0 & (HWc-1));

    if (t < 96) bs[t] = (t < 32) ? bk[t] : (t < 64) ? bq[t-32] : bx[t-64];
    if (t < 64) vs[t] = vessel[p0 + t];

    int ms = w & 3;
    int nh = w >> 2;
    int m0 = ms * 16;

    float acc[6][4];
#pragma unroll
    for (int i = 0; i < 6; ++i)
#pragma unroll
        for (int j = 0; j < 4; ++j) acc[i][j] = 0.f;

    int a_row = m0 + (lane & 15);
    int a_col = ((lane >> 4) << 3);
    int b_row = lane & 7;
    int b_col = ((lane >> 3) & 1) << 3;

    uint32_t AhB = smem_u32(Ah), AlB = smem_u32(Al);
    uint32_t BhB = smem_u32(Bh), BlB = smem_u32(Bl);
    uint32_t aOff = (uint32_t)(a_row*72 + a_col) * 2u;
    uint32_t bOffL = (uint32_t)(b_row*72 + b_col) * 2u;

    for (int c0 = 0; c0 < 256; c0 += 64) {
        __syncthreads();
#pragma unroll
        for (int i = 0; i < 16; ++i) {
            int idx = i*256 + t;
            int px = idx & 63, cc = idx >> 6;
            float v = xb[(size_t)(c0+cc)*HWc + px];
            __nv_bfloat16 h = __float2bfloat16(v);
            __nv_bfloat16 l = __float2bfloat16(v - __bfloat162float(h));
            Ah[px*72 + cc] = h;
            Al[px*72 + cc] = l;
        }
#pragma unroll
        for (int i = 0; i < 24; ++i) {
            int idx = i*256 + t;
            int k = idx & 63, o = idx >> 6;
            const float* W = (o < 32) ? wk : (o < 64) ? wq : wx;
            float v = W[(o & 31)*256 + c0 + k];
            __nv_bfloat16 h = __float2bfloat16(v);
            __nv_bfloat16 l = __float2bfloat16(v - __bfloat162float(h));
            Bh[o*72 + k] = h;
            Bl[o*72 + k] = l;
        }
        __syncthreads();

#pragma unroll
        for (int ks = 0; ks < 4; ++ks) {
            uint32_t kByte = (uint32_t)(ks*16) * 2u;
            uint32_t ah0,ah1,ah2,ah3, al0,al1,al2,al3;
            LDMX4(ah0,ah1,ah2,ah3, AhB + aOff + kByte);
            LDMX4(al0,al1,al2,al3, AlB + aOff + kByte);
#pragma unroll
            for (int nt = 0; nt < 6; ++nt) {
                uint32_t nByte = (uint32_t)((nh*48 + nt*8)*72) * 2u;
                uint32_t bh0,bh1, bl0,bl1;
                LDMX2(bh0,bh1, BhB + bOffL + nByte + kByte);
                LDMX2(bl0,bl1, BlB + bOffL + nByte + kByte);
                MMA16816(acc[nt], ah0,ah1,ah2,ah3, bh0,bh1);
                MMA16816(acc[nt], al0,al1,al2,al3, bh0,bh1);
                MMA16816(acc[nt], ah0,ah1,ah2,ah3, bl0,bl1);
            }
        }
    }

    int r  = lane >> 2;
    int c2 = (lane & 3) * 2;
    int px0 = m0 + r, px1 = m0 + r + 8;
    int pA = p0 + px0, pB = p0 + px1;
    float v0 = vs[px0], v1 = vs[px1];
#pragma unroll
    for (int nt = 0; nt < 6; ++nt) {
        int n0  = nh*48 + nt*8;
        int mat = n0 >> 5;
        int ch  = (n0 + c2) & 31;
        float* dst = (mat == 0) ? g_km : (mat == 1) ? g_qm : g_xm;
        float s0 = (mat == 0) ? v0 : 1.f;
        float s1 = (mat == 0) ? v1 : 1.f;
        float b0 = bs[n0 + c2], b1 = bs[n0 + c2 + 1];
        float2 o0 = make_float2((acc[nt][0] + b0) * s0, (acc[nt][1] + b1) * s0);
        float2 o1 = make_float2((acc[nt][2] + b0) * s1, (acc[nt][3] + b1) * s1);
        *(float2*)(dst + (size_t)pA*CPc + ch) = o0;
        *(float2*)(dst + (size_t)pB*CPc + ch) = o1;
    }
}

// ---------------------------------------------------------------------------
// K2a (HMMA scores + softmax): block = one image row (64 px), 256 thr.
// Stage km rows h-4..h+4 as zero-padded 72-halo tiles (hi/lo, stride 40) and
// qm row (hi/lo). Per dy: banded S = Q.KM^T (each 16-px m-strip needs only
// n-tiles m0, m0+8, m0+16 in halo coords since q <= k_h <= q+8).
// Scatter band elements to sw[64][96], nested softmax, write e*coef to g_w.
// ---------------------------------------------------------------------------
#define K2_KMH 0
#define K2_KML (9*72*40*2)
#define K2_QH  (2*9*72*40*2)
#define K2_QL  (2*9*72*40*2 + 64*40*2)
#define K2_SW  (2*9*72*40*2 + 2*64*40*2)
#define K2_SMEM (K2_SW + 64*96*4)       // 103680+10240+24576 = 138496 B

__global__ void __launch_bounds__(256) k2a_scores()
{
    extern __shared__ __align__(16) char dsm[];
    __nv_bfloat16* KMh = (__nv_bfloat16*)(dsm + K2_KMH);
    __nv_bfloat16* KMl = (__nv_bfloat16*)(dsm + K2_KML);
    __nv_bfloat16* Qh  = (__nv_bfloat16*)(dsm + K2_QH);
    __nv_bfloat16* Ql  = (__nv_bfloat16*)(dsm + K2_QL);
    float*         sw  = (float*)(dsm + K2_SW);

    int t = threadIdx.x;
    int w = t >> 5, lane = t & 31;
    int blk = blockIdx.x;
    int b = blk >> 6, h = blk & 63;

    // ---- stage KM halo tiles (hi/lo), zero-filled OOB ----
    const float4* km4 = (const float4*)(g_km + (size_t)b*HWc*CPc);
#pragma unroll
    for (int dy = 0; dy < 9; ++dy) {
        int hh = h + dy - 4;
        bool rowok = ((unsigned)hh < 64u);
#pragma unroll
        for (int j = 0; j < 3; ++j) {
            int idx = j*256 + t;                  // 576 float4 per plane
            if (idx < 576) {
                int kh = idx >> 3, c4 = (idx & 7)*4;
                int k = kh - 4;
                float4 v = make_float4(0.f,0.f,0.f,0.f);
                if (rowok && ((unsigned)k < 64u))
                    v = km4[(size_t)(hh*64 + k)*8 + (c4>>2)];
                float vv[4] = {v.x, v.y, v.z, v.w};
                int base = (dy*72 + kh)*40 + c4;
#pragma unroll
                for (int q = 0; q < 4; ++q) {
                    __nv_bfloat16 hi = __float2bfloat16(vv[q]);
                    __nv_bfloat16 lo = __float2bfloat16(vv[q] - __bfloat162float(hi));
                    KMh[base + q] = hi;
                    KMl[base + q] = lo;
                }
            }
        }
    }
    // ---- stage Q row (hi/lo) ----
    const float4* qm4 = (const float4*)(g_qm + (size_t)(b*HWc + h*64)*CPc);
#pragma unroll
    for (int i = 0; i < 2; ++i) {
        int idx = i*256 + t;                      // 512 float4
        int px = idx >> 3, c4 = (idx & 7)*4;
        float4 v = qm4[idx];
        float vv[4] = {v.x, v.y, v.z, v.w};
        int base = px*40 + c4;
#pragma unroll
        for (int q = 0; q < 4; ++q) {
            __nv_bfloat16 hi = __float2bfloat16(vv[q]);
            __nv_bfloat16 lo = __float2bfloat16(vv[q] - __bfloat162float(hi));
            Qh[base + q] = hi;
            Ql[base + q] = lo;
        }
    }
    __syncthreads();

    // ---- banded score GEMMs ----
    int ms = w & 3;          // m-strip (16 q-pixels)
    int hdy = w >> 2;        // dy half: 0 -> dy 0..4, 1 -> dy 5..8
    int m0 = ms * 16;
    int dy0 = hdy ? 5 : 0;
    int dyN = hdy ? 4 : 5;

    int a_row = m0 + (lane & 15);
    int a_col = ((lane >> 4) << 3);
    int b_row = lane & 7;
    int b_col = ((lane >> 3) & 1) << 3;
    uint32_t QhB = smem_u32(Qh), QlB = smem_u32(Ql);
    uint32_t KMhB = smem_u32(KMh), KMlB = smem_u32(KMl);
    uint32_t aOff  = (uint32_t)(a_row*40 + a_col) * 2u;
    uint32_t bOffL = (uint32_t)(b_row*40 + b_col) * 2u;

    // hoist Q frags (2 k-steps)
    uint32_t qh[2][4], ql[2][4];
#pragma unroll
    for (int ks = 0; ks < 2; ++ks) {
        uint32_t kByte = (uint32_t)(ks*16) * 2u;
        LDMX4(qh[ks][0],qh[ks][1],qh[ks][2],qh[ks][3], QhB + aOff + kByte);
        LDMX4(ql[ks][0],ql[ks][1],ql[ks][2],ql[ks][3], QlB + aOff + kByte);
    }

    int r  = lane >> 2;
    int c2 = (lane & 3) * 2;
#pragma unroll 1
    for (int dyi = 0; dyi < 5; ++dyi) {
        if (dyi >= dyN) break;
        int dy = dy0 + dyi;
        uint32_t dyBase = (uint32_t)(dy*72*40) * 2u;
#pragma unroll
        for (int nt = 0; nt < 3; ++nt) {
            uint32_t nByte = dyBase + (uint32_t)((m0 + nt*8)*40) * 2u;
            float acc[4] = {0.f, 0.f, 0.f, 0.f};
#pragma unroll
            for (int ks = 0; ks < 2; ++ks) {
                uint32_t kByte = (uint32_t)(ks*16) * 2u;
                uint32_t bh0,bh1, bl0,bl1;
                LDMX2(bh0,bh1, KMhB + bOffL + nByte + kByte);
                LDMX2(bl0,bl1, KMlB + bOffL + nByte + kByte);
                MMA16816(acc, qh[ks][0],qh[ks][1],qh[ks][2],qh[ks][3], bh0,bh1);
                MMA16816(acc, ql[ks][0],ql[ks][1],ql[ks][2],ql[ks][3], bh0,bh1);
                MMA16816(acc, qh[ks][0],qh[ks][1],qh[ks][2],qh[ks][3], bl0,bl1);
            }
            // scatter band elements: j_dx = k_h - q, valid 0..8
            int d = nt*8 + c2 - r;
            int jb = dy*9;
            if ((unsigned)d <= 8u)       sw[(m0+r)*96   + jb + d]     = acc[0];
            if ((unsigned)(d+1) <= 8u)   sw[(m0+r)*96   + jb + d + 1] = acc[1];
            int d2 = d - 8;
            if ((unsigned)d2 <= 8u)      sw[(m0+r+8)*96 + jb + d2]     = acc[2];
            if ((unsigned)(d2+1) <= 8u)  sw[(m0+r+8)*96 + jb + d2 + 1] = acc[3];
        }
    }
    __syncthreads();

    // ---- softmax: 4 threads per pixel ----
    int q = t >> 2, sub = t & 3;
    float* sq = &sw[q*96];
    float z1=0.f, z2=0.f, z3=0.f, z4=0.f;
#pragma unroll
    for (int dy = 0; dy < 9; ++dy) {
        for (int dd = sub; dd < 9; dd += 4) {
            int ady = (dy > 4) ? dy-4 : 4-dy;
            int add = (dd > 4) ? dd-4 : 4-dd;
            int a = (ady > add) ? ady : add;
            float e = __expf(sq[dy*9 + dd]);
            sq[dy*9 + dd] = e;
            z4 += e;
            if (a <= 3) z3 += e;
            if (a <= 2) z2 += e;
            if (a <= 1) z1 += e;
        }
    }
    z1 += __shfl_xor_sync(0xffffffffu, z1, 1);  z1 += __shfl_xor_sync(0xffffffffu, z1, 2);
    z2 += __shfl_xor_sync(0xffffffffu, z2, 1);  z2 += __shfl_xor_sync(0xffffffffu, z2, 2);
    z3 += __shfl_xor_sync(0xffffffffu, z3, 1);  z3 += __shfl_xor_sync(0xffffffffu, z3, 2);
    z4 += __shfl_xor_sync(0xffffffffu, z4, 1);  z4 += __shfl_xor_sync(0xffffffffu, z4, 2);
    float i4 = 1.0f/z4, i3 = 1.0f/z3, i2 = 1.0f/z2, i1 = 1.0f/z1;
    float cc4 = i4, cc3 = i4+i3, cc2 = i4+i3+i2, cc1 = i4+i3+i2+i1;
#pragma unroll
    for (int dy = 0; dy < 9; ++dy) {
        for (int dd = sub; dd < 9; dd += 4) {
            int ady = (dy > 4) ? dy-4 : 4-dy;
            int add = (dd > 4) ? dd-4 : 4-dd;
            int a = (ady > add) ? ady : add;
            float coef = (a <= 1) ? cc1 : (a == 2) ? cc2 : (a == 3) ? cc3 : cc4;
            sq[dy*9 + dd] *= coef;
        }
    }
    __syncthreads();

    // ---- write weights to gmem: g_w[p][96] ----
    float* wout = g_w + (size_t)(b*HWc + h*64 + (t >> 2)) * 96 + (t & 3)*24;
    const float* win = &sw[(t >> 2)*96 + (t & 3)*24];
#pragma unroll
    for (int i = 0; i < 6; ++i)
        *(float4*)(wout + i*4) = *(const float4*)(win + i*4);
}

// ---------------------------------------------------------------------------
// K2b (value pass): proven geometry (warp = 4 px, 8 lanes/px, 4 ch/lane),
// weights read from g_w (broadcast LDG) — no scores, no shfl, no exp.
// ---------------------------------------------------------------------------
__global__ void k2b_values()
{
    int t    = threadIdx.x;
    int lane = t & 31, warp = t >> 5;
    int pxg  = lane >> 3;
    int cg   = lane & 7;
    int p  = blockIdx.x * 16 + warp * 4 + pxg;
    int hw = p & (HWc-1);
    int h  = hw >> 6, w = hw & 63;

    const float* xmrow = g_xm + (size_t)p*CPc + cg*4;
    const float* wrow  = g_w + (size_t)p*96;

    float ax=0.f, ay=0.f, az=0.f, aw=0.f;
#pragma unroll
    for (int dy = -4; dy <= 4; ++dy) {
#pragma unroll
        for (int dx = -4; dx <= 4; ++dx) {
            bool ok = ((unsigned)(h+dy) < 64u) && ((unsigned)(w+dx) < 64u);
            if (!ok) continue;   // OOB value == 0
            float wj = wrow[(dy+4)*9 + dx + 4];
            float4 xm4 = *(const float4*)(xmrow + (dy*64+dx)*CPc);
            ax += wj*xm4.x; ay += wj*xm4.y; az += wj*xm4.z; aw += wj*xm4.w;
        }
    }
    *(float4*)(g_pre + (size_t)p*CPc + cg*4) = make_float4(ax, ay, az, aw);
}

// ---------------------------------------------------------------------------
// K3: fused BN-stats (unchanged)
// ---------------------------------------------------------------------------
__global__ void k3_stats(const float* __restrict__ wf, const float* __restrict__ bf,
                         const float* __restrict__ gamma, const float* __restrict__ beta)
{
    __shared__ __align__(16) float ps[256*32];
    int t = threadIdx.x;
    size_t base = (size_t)blockIdx.x * 256 * 32;
#pragma unroll
    for (int i = 0; i < 32; ++i)
        ps[i*256 + t] = g_pre[base + i*256 + t];
    __syncthreads();

    int i  = t >> 3;
    int j4 = (t & 7) * 4;
    float s0=0.f, s1=0.f, s2=0.f, s3=0.f;
    for (int p = 0; p < 256; ++p) {
        float a  = ps[p*32 + i];
        float4 b = *(const float4*)&ps[p*32 + j4];
        s0 += a*b.x; s1 += a*b.y; s2 += a*b.z; s3 += a*b.w;
    }
    float* part = g_part + blockIdx.x * 1056;
    part[32 + i*32 + j4 + 0] = s0;
    part[32 + i*32 + j4 + 1] = s1;
    part[32 + i*32 + j4 + 2] = s2;
    part[32 + i*32 + j4 + 3] = s3;
    if (t < 32) {
        float mm = 0.f;
        for (int p = 0; p < 256; ++p) mm += ps[p*32 + t];
        part[t] = mm;
    }
    __threadfence();
    __syncthreads();

    __shared__ unsigned int amLast;
    if (t == 0) amLast = atomicAdd(&g_cnt, 1u);
    __syncthreads();
    if (amLast != 63u) return;

    float* S = ps;
    for (int e = t; e < 1056; e += 256) {
        float s = 0.f;
#pragma unroll
        for (int b = 0; b < 64; ++b) s += g_part[b*1056 + e];
        S[e] = s * (1.0f/16384.0f);
    }
    __syncthreads();

    {
        float wreg[32];
#pragma unroll
        for (int c = 0; c < 32; ++c) wreg[c] = wf[t*32 + c];
        float wmu = 0.f;
#pragma unroll
        for (int c = 0; c < 32; ++c) wmu += wreg[c] * S[c];
        float qf = 0.f;
        for (int c = 0; c < 32; ++c) {
            float tc = 0.f;
#pragma unroll
            for (int d = 0; d < 32; ++d) tc += S[32 + c*32 + d] * wreg[d];
            qf += wreg[c] * tc;
        }
        float var   = qf - wmu*wmu;
        float meanY = wmu + bf[t];
        float a = gamma[t] * rsqrtf(var + EPSc);
        g_ab[t]       = a;
        g_ab[256 + t] = beta[t] - a * meanY;
    }
    if (t == 0) g_cnt = 0u;
}

// ---------------------------------------------------------------------------
// K4 (HMMA): out = x + a*(pre.wf^T) + bb  (R16 PROVEN version, unchanged)
// ---------------------------------------------------------------------------
#define K4_AH  0
#define K4_AL  (128*48*2)
#define K4_BH  (2*128*48*2)
#define K4_BL  (2*128*48*2 + 64*48*2)
#define K4_SY  (2*128*48*2 + 2*64*48*2)
#define K4_SMEM (K4_SY + 128*72*4)

__global__ void __launch_bounds__(256) k4_mma(
    const float* __restrict__ x, const float* __restrict__ wf,
    const float* __restrict__ bf, float* __restrict__ out)
{
    extern __shared__ __align__(16) char dsm[];
    __nv_bfloat16* Ah = (__nv_bfloat16*)(dsm + K4_AH);
    __nv_bfloat16* Al = (__nv_bfloat16*)(dsm + K4_AL);
    __nv_bfloat16* Bh = (__nv_bfloat16*)(dsm + K4_BH);
    __nv_bfloat16* Bl = (__nv_bfloat16*)(dsm + K4_BL);
    float*         sy = (float*)(dsm + K4_SY);
    __shared__ float as[64], bbs[64];

    int t = threadIdx.x;
    int w = t >> 5, lane = t & 31;
    int cog = blockIdx.y * 64;
    int p0  = blockIdx.x * 128;

    const float4* pre4 = (const float4*)(g_pre + (size_t)p0*32);
#pragma unroll
    for (int i = 0; i < 4; ++i) {
        int idx = i*256 + t;
        int px = idx >> 3, c4 = (idx & 7)*4;
        float4 v = pre4[idx];
        float vv[4] = {v.x, v.y, v.z, v.w};
#pragma unroll
        for (int j = 0; j < 4; ++j) {
            __nv_bfloat16 h = __float2bfloat16(vv[j]);
            __nv_bfloat16 l = __float2bfloat16(vv[j] - __bfloat162float(h));
            Ah[px*48 + c4 + j] = h;
            Al[px*48 + c4 + j] = l;
        }
    }
#pragma unroll
    for (int i = 0; i < 8; ++i) {
        int idx = i*256 + t;
        int o = idx >> 5, c = idx & 31;
        float v = wf[(size_t)(cog+o)*32 + c];
        __nv_bfloat16 h = __float2bfloat16(v);
        __nv_bfloat16 l = __float2bfloat16(v - __bfloat162float(h));
        Bh[o*48 + c] = h;
        Bl[o*48 + c] = l;
    }
    if (t < 64) {
        float a = g_ab[cog+t];
        as[t]  = a;
        bbs[t] = g_ab[256+cog+t] + a * bf[cog+t];
    }
    __syncthreads();

    int m0 = w * 16;
    float acc[8][4];
#pragma unroll
    for (int i = 0; i < 8; ++i)
#pragma unroll
        for (int j = 0; j < 4; ++j) acc[i][j] = 0.f;

    int a_row = m0 + (lane & 15);
    int a_col = ((lane >> 4) << 3);
    int b_row = lane & 7;
    int b_col = ((lane >> 3) & 1) << 3;
    uint32_t AhB = smem_u32(Ah), AlB = smem_u32(Al);
    uint32_t BhB = smem_u32(Bh), BlB = smem_u32(Bl);
    uint32_t aOff  = (uint32_t)(a_row*48 + a_col) * 2u;
    uint32_t bOffL = (uint32_t)(b_row*48 + b_col) * 2u;

#pragma unroll
    for (int ks = 0; ks < 2; ++ks) {
        uint32_t kByte = (uint32_t)(ks*16) * 2u;
        uint32_t ah0,ah1,ah2,ah3, al0,al1,al2,al3;
        LDMX4(ah0,ah1,ah2,ah3, AhB + aOff + kByte);
        LDMX4(al0,al1,al2,al3, AlB + aOff + kByte);
#pragma unroll
        for (int nt = 0; nt < 8; ++nt) {
            uint32_t nByte = (uint32_t)((nt*8)*48) * 2u;
            uint32_t bh0,bh1, bl0,bl1;
            LDMX2(bh0,bh1, BhB + bOffL + nByte + kByte);
            LDMX2(bl0,bl1, BlB + bOffL + nByte + kByte);
            MMA16816(acc[nt], ah0,ah1,ah2,ah3, bh0,bh1);
            MMA16816(acc[nt], al0,al1,al2,al3, bh0,bh1);
            MMA16816(acc[nt], ah0,ah1,ah2,ah3, bl0,bl1);
        }
    }

    int r  = lane >> 2;
    int c2 = (lane & 3) * 2;
#pragma unroll
    for (int nt = 0; nt < 8; ++nt) {
        int col = nt*8 + c2;
        sy[(m0 + r)*72 + col]     = acc[nt][0];
        sy[(m0 + r)*72 + col + 1] = acc[nt][1];
        sy[(m0 + r + 8)*72 + col]     = acc[nt][2];
        sy[(m0 + r + 8)*72 + col + 1] = acc[nt][3];
    }
    __syncthreads();

    int px   = t & 127;
    int half = t >> 7;
    int p = p0 + px;
    int b = p >> 12, hw = p & 4095;
    const float* xrow = x   + (size_t)b*(Cc*HWc) + hw;
    float*       orow = out + (size_t)b*(Cc*HWc) + hw;
    const float* yrow = &sy[px*72 + half*32];
#pragma unroll
    for (int cc = 0; cc < 32; ++cc) {
        int co = half*32 + cc;
        size_t off = (size_t)(cog + co) * HWc;
        orow[off] = xrow[off] + as[co]*yrow[cc] + bbs[co];
    }
}

// ---------------------------------------------------------------------------
extern "C" void kernel_launch(void* const* d_in, const int* in_sizes, int n_in,
                              void* d_out, int out_size)
{
    const float* x      = (const float*)d_in[0];
    const float* vessel = (const float*)d_in[1];
    const float* wk     = (const float*)d_in[2];
    const float* bk     = (const float*)d_in[3];
    const float* wq     = (const float*)d_in[4];
    const float* bq     = (const float*)d_in[5];
    const float* wx     = (const float*)d_in[6];
    const float* bx     = (const float*)d_in[7];
    const float* wf     = (const float*)d_in[8];
    const float* bf     = (const float*)d_in[9];
    const float* gamma  = (const float*)d_in[10];
    const float* beta   = (const float*)d_in[11];
    float* out = (float*)d_out;

    cudaFuncSetAttribute(k2a_scores, cudaFuncAttributeMaxDynamicSharedMemorySize, K2_SMEM);
    cudaFuncSetAttribute(k4_mma, cudaFuncAttributeMaxDynamicSharedMemorySize, K4_SMEM);

    k1_kqx_mma<<<256, 256>>>(x, vessel, wk, bk, wq, bq, wx, bx);
    k2a_scores<<<256, 256, K2_SMEM>>>();
    k2b_values<<<1024, 128>>>();
    k3_stats<<<64, 256>>>(wf, bf, gamma, beta);
    k4_mma<<<dim3(128,4), 256, K4_SMEM>>>(x, wf, bf, out);
}